// round 2
// baseline (speedup 1.0000x reference)
#include <cuda_runtime.h>
#include <cstdint>

// ---------------------------------------------------------------------------
// CausalSelfAttention: B=4, S=2048, D=1024, fp32, causal softmax (scale 1/32)
//   q = x@Wq^T ; k = x@Wk^T ; v = x@Wv^T
//   S = q@k^T (causal) ; P = softmax(S/32) ; out = P@v
// Pipeline: [proj GEMM x3] -> [scores GEMM (lower-tri tiles)] -> [row softmax]
//           -> [PV GEMM (k-tiles <= q-tile)]
// All GEMMs: tf32 mma.sync m16n8k8, 128x128x16 tiles, cp.async double buffer.
// ---------------------------------------------------------------------------

#define BATCH 4
#define SEQ   2048
#define DIM   1024
#define NQT   (SEQ / 128)                 // 16 q-tiles
#define NTRI  (NQT * (NQT + 1) / 2)       // 136 lower-tri tiles

// Scratch (static __device__ globals: allocation-free per harness rules)
__device__ float g_Q[(size_t)BATCH * SEQ * DIM];
__device__ float g_K[(size_t)BATCH * SEQ * DIM];
__device__ float g_V[(size_t)BATCH * SEQ * DIM];
__device__ float g_S[(size_t)BATCH * SEQ * SEQ];

// ---------------------------------------------------------------------------
// helpers
// ---------------------------------------------------------------------------
__device__ __forceinline__ uint32_t f2tf32(float f) {
    uint32_t u;
    asm("cvt.rna.tf32.f32 %0, %1;" : "=r"(u) : "f"(f));
    return u;
}

__device__ __forceinline__ void mma_tf32(float* d, const uint32_t* a,
                                         const uint32_t* b, const float* c) {
    asm volatile(
        "mma.sync.aligned.m16n8k8.row.col.f32.tf32.tf32.f32 "
        "{%0,%1,%2,%3}, {%4,%5,%6,%7}, {%8,%9}, {%10,%11,%12,%13};\n"
        : "=f"(d[0]), "=f"(d[1]), "=f"(d[2]), "=f"(d[3])
        : "r"(a[0]), "r"(a[1]), "r"(a[2]), "r"(a[3]),
          "r"(b[0]), "r"(b[1]),
          "f"(c[0]), "f"(c[1]), "f"(c[2]), "f"(c[3]));
}

__device__ __forceinline__ void cpa16(void* smem, const void* g) {
    uint32_t s = (uint32_t)__cvta_generic_to_shared(smem);
    asm volatile("cp.async.cg.shared.global [%0], [%1], 16;\n" :: "r"(s), "l"(g));
}
#define CP_COMMIT() asm volatile("cp.async.commit_group;\n")
#define CP_WAIT(n)  asm volatile("cp.async.wait_group %0;\n" :: "n"(n))

// ---------------------------------------------------------------------------
// Generic 128x128 tile GEMM core.
// C[row0+m, col0+n] = sum_k A[row0+m, k] * B(k, col0+n)
//   MODE 0: B stored [n][k] row-major (k contiguous)   -> C = A @ B^T
//   MODE 1: B stored [k][n] row-major (n contiguous)   -> C = A @ B
// A always row-major [m][k]. kIters = K / 16.
// 256 threads: 8 warps as 2(m) x 4(n); warp tile 64x32; 4x4 m16n8k8 frags.
// ---------------------------------------------------------------------------
template <int MODE>
__device__ __forceinline__ void gemm_core(const float* __restrict__ A,
                                          const float* __restrict__ Bm,
                                          float* __restrict__ C,
                                          int lda, int ldb, int ldc,
                                          int kIters, int row0, int col0) {
    constexpr int BM = 128, BN = 128, BK = 16;
    constexpr int BROWS = (MODE == 0) ? BN : BK;
    constexpr int BCOLS = (MODE == 0) ? BK : BN;
    constexpr int BPAD  = (MODE == 0) ? 4  : 8;

    __shared__ float As[2][BM][BK + 4];
    __shared__ float Bs[2][BROWS][BCOLS + BPAD];

    const int tid  = threadIdx.x;
    const int warp = tid >> 5;
    const int lane = tid & 31;
    const int wm   = (warp >> 2) * 64;  // 0 / 64
    const int wn   = (warp & 3) * 32;   // 0,32,64,96
    const int gid  = lane >> 2;         // 0..7
    const int tig  = lane & 3;          // 0..3

    float acc[4][4][4];
#pragma unroll
    for (int i = 0; i < 4; i++)
#pragma unroll
        for (int j = 0; j < 4; j++)
#pragma unroll
            for (int r = 0; r < 4; r++) acc[i][j][r] = 0.f;

    auto loadA = [&](int kt, int buf) {
#pragma unroll
        for (int i = 0; i < 2; i++) {
            int f = tid + i * 256;
            int r = f >> 2, q = f & 3;
            cpa16(&As[buf][r][q * 4],
                  &A[(size_t)(row0 + r) * lda + kt * BK + q * 4]);
        }
    };
    auto loadB = [&](int kt, int buf) {
        if (MODE == 0) {
#pragma unroll
            for (int i = 0; i < 2; i++) {
                int f = tid + i * 256;
                int r = f >> 2, q = f & 3;  // r = n, q*4 = k
                cpa16(&Bs[buf][r][q * 4],
                      &Bm[(size_t)(col0 + r) * ldb + kt * BK + q * 4]);
            }
        } else {
#pragma unroll
            for (int i = 0; i < 2; i++) {
                int f = tid + i * 256;
                int r = f >> 5, q = f & 31;  // r = k (0..15), q*4 = n
                cpa16(&Bs[buf][r][q * 4],
                      &Bm[(size_t)(kt * BK + r) * ldb + col0 + q * 4]);
            }
        }
    };

    loadA(0, 0);
    loadB(0, 0);
    CP_COMMIT();

    int buf = 0;
    for (int kt = 0; kt < kIters; kt++) {
        if (kt + 1 < kIters) {
            loadA(kt + 1, buf ^ 1);
            loadB(kt + 1, buf ^ 1);
            CP_COMMIT();
            CP_WAIT(1);
        } else {
            CP_WAIT(0);
        }
        __syncthreads();

#pragma unroll
        for (int ks = 0; ks < 2; ks++) {
            const int kk = ks * 8;
            uint32_t af[4][4];
#pragma unroll
            for (int mf = 0; mf < 4; mf++) {
                int r = wm + mf * 16 + gid;
                af[mf][0] = f2tf32(As[buf][r][kk + tig]);
                af[mf][1] = f2tf32(As[buf][r + 8][kk + tig]);
                af[mf][2] = f2tf32(As[buf][r][kk + tig + 4]);
                af[mf][3] = f2tf32(As[buf][r + 8][kk + tig + 4]);
            }
            uint32_t bf[4][2];
#pragma unroll
            for (int nf = 0; nf < 4; nf++) {
                int n = wn + nf * 8 + gid;
                if (MODE == 0) {
                    bf[nf][0] = f2tf32(Bs[buf][n][kk + tig]);
                    bf[nf][1] = f2tf32(Bs[buf][n][kk + tig + 4]);
                } else {
                    bf[nf][0] = f2tf32(Bs[buf][kk + tig][n]);
                    bf[nf][1] = f2tf32(Bs[buf][kk + tig + 4][n]);
                }
            }
#pragma unroll
            for (int mf = 0; mf < 4; mf++)
#pragma unroll
                for (int nf = 0; nf < 4; nf++)
                    mma_tf32(acc[mf][nf], af[mf], bf[nf], acc[mf][nf]);
        }
        __syncthreads();
        buf ^= 1;
    }

    // epilogue: direct global stores
#pragma unroll
    for (int mf = 0; mf < 4; mf++) {
#pragma unroll
        for (int nf = 0; nf < 4; nf++) {
            int r = row0 + wm + mf * 16 + gid;
            int c = col0 + wn + nf * 8 + tig * 2;
            C[(size_t)r * ldc + c]           = acc[mf][nf][0];
            C[(size_t)r * ldc + c + 1]       = acc[mf][nf][1];
            C[(size_t)(r + 8) * ldc + c]     = acc[mf][nf][2];
            C[(size_t)(r + 8) * ldc + c + 1] = acc[mf][nf][3];
        }
    }
}

// ---------------------------------------------------------------------------
// kernels
// ---------------------------------------------------------------------------
__global__ __launch_bounds__(256) void proj_kernel(const float* __restrict__ x,
                                                   const float* __restrict__ Wq,
                                                   const float* __restrict__ Wk,
                                                   const float* __restrict__ Wv) {
    const float* W = (blockIdx.z == 0) ? Wq : (blockIdx.z == 1) ? Wk : Wv;
    float* O = (blockIdx.z == 0) ? g_Q : (blockIdx.z == 1) ? g_K : g_V;
    gemm_core<0>(x, W, O, DIM, DIM, DIM, DIM / 16,
                 blockIdx.y * 128, blockIdx.x * 128);
}

// lower-triangular tile index -> (qt, kt)
__device__ __forceinline__ void tri_decode(int t, int& qt, int& kt) {
    // qt is the smallest q with (q+1)(q+2)/2 > t
    int q = (int)((sqrtf(8.0f * t + 1.0f) - 1.0f) * 0.5f);
    while ((q + 1) * (q + 2) / 2 <= t) q++;
    while (q * (q + 1) / 2 > t) q--;
    qt = q;
    kt = t - q * (q + 1) / 2;
}

__global__ __launch_bounds__(256) void scores_kernel() {
    int qt, kt;
    tri_decode(blockIdx.x, qt, kt);
    int b = blockIdx.z;
    const float* Qp = g_Q + (size_t)b * SEQ * DIM;
    const float* Kp = g_K + (size_t)b * SEQ * DIM;
    float* Sp = g_S + (size_t)b * SEQ * SEQ;
    gemm_core<0>(Qp, Kp, Sp, DIM, DIM, SEQ, DIM / 16, qt * 128, kt * 128);
}

__global__ __launch_bounds__(256) void softmax_kernel() {
    const int row = blockIdx.x;  // 0..B*S-1
    const int b = row / SEQ, q = row % SEQ;
    float* p = g_S + (size_t)b * SEQ * SEQ + (size_t)q * SEQ;
    const int len  = q + 1;
    const int kend = ((q / 128) + 1) * 128;  // PV reads k < (qt+1)*128
    const float scale = 0.03125f;            // 1/sqrt(1024)

    __shared__ float red[8];
    __shared__ float red2[8];

    // pass 1: load row into registers (<= 8 per thread) + max
    float vals[8];
    int cnt = 0;
    float m = -1e30f;
    for (int i = threadIdx.x; i < len; i += 256) {
        float v = p[i];
        vals[cnt++] = v;
        m = fmaxf(m, v);
    }
#pragma unroll
    for (int o = 16; o; o >>= 1) m = fmaxf(m, __shfl_xor_sync(~0u, m, o));
    if ((threadIdx.x & 31) == 0) red[threadIdx.x >> 5] = m;
    __syncthreads();
    m = red[0];
#pragma unroll
    for (int i = 1; i < 8; i++) m = fmaxf(m, red[i]);

    // pass 2: exp in registers + sum
    float s = 0.f;
#pragma unroll 8
    for (int j = 0; j < cnt; j++) {
        float e = __expf(scale * (vals[j] - m));
        vals[j] = e;
        s += e;
    }
#pragma unroll
    for (int o = 16; o; o >>= 1) s += __shfl_xor_sync(~0u, s, o);
    if ((threadIdx.x & 31) == 0) red2[threadIdx.x >> 5] = s;
    __syncthreads();
    s = 0.f;
#pragma unroll
    for (int i = 0; i < 8; i++) s += red2[i];
    const float inv = 1.0f / s;

    // write back normalized probs + zero tail up to tile boundary
    cnt = 0;
    for (int i = threadIdx.x; i < len; i += 256) p[i] = vals[cnt++] * inv;
    for (int i = len + threadIdx.x; i < kend; i += 256) p[i] = 0.f;
}

__global__ __launch_bounds__(256) void pv_kernel(float* __restrict__ out) {
    int qt = blockIdx.y, et = blockIdx.x, b = blockIdx.z;
    const float* P = g_S + (size_t)b * SEQ * SEQ;
    const float* V = g_V + (size_t)b * SEQ * DIM;
    float* O = out + (size_t)b * SEQ * DIM;
    // causal: k-tiles 0..qt only => kIters = (qt+1)*128/16
    gemm_core<1>(P, V, O, SEQ, DIM, DIM, (qt + 1) * 8, qt * 128, et * 128);
}

// ---------------------------------------------------------------------------
// launch
// ---------------------------------------------------------------------------
extern "C" void kernel_launch(void* const* d_in, const int* in_sizes, int n_in,
                              void* d_out, int out_size) {
    // inputs per metadata order: x [B,S,D], Wq [D,D], Wk [D,D], Wv [D,D]
    int xi = 0;
    for (int i = 0; i < n_in; i++)
        if (in_sizes[i] == BATCH * SEQ * DIM) { xi = i; break; }
    const float* x  = (const float*)d_in[xi];
    const float* w[3];
    int wi = 0;
    for (int i = 0; i < n_in && wi < 3; i++)
        if (i != xi) w[wi++] = (const float*)d_in[i];
    const float* Wq = w[0];
    const float* Wk = w[1];
    const float* Wv = w[2];
    float* out = (float*)d_out;

    proj_kernel<<<dim3(8, 64, 3), 256>>>(x, Wq, Wk, Wv);
    scores_kernel<<<dim3(NTRI, 1, 4), 256>>>();
    softmax_kernel<<<BATCH * SEQ, 256>>>();
    pv_kernel<<<dim3(8, 16, 4), 256>>>(out);
}